// round 2
// baseline (speedup 1.0000x reference)
#include <cuda_runtime.h>
#include <cuda_fp16.h>
#include <mma.h>

using namespace nvcuda;

#define N_TOK 16384
#define DIN   512
#define DOUT  512
#define NEXP  16

#define BM 128
#define BN 128
#define BK 32

// ---------------- device scratch (no allocations allowed) ----------------
__device__ int   g_cnt[NEXP];
__device__ int   g_perm[NEXP * N_TOK];
__device__ float g_pw  [NEXP * N_TOK];

__global__ void zero_cnt_kernel() {
    if (threadIdx.x < NEXP) g_cnt[threadIdx.x] = 0;
}

// ---------------- router: fp32 logits, top-2 + softmax, scatter ----------
// block = 256 threads (8 warps); each warp handles 8 tokens sequentially.
__global__ void router_kernel(const float* __restrict__ x,
                              const float* __restrict__ gw,   // [DIN, NEXP]
                              const float* __restrict__ gb) { // [NEXP]
    __shared__ float sgwT[NEXP * DIN];  // transposed: [e][k] for conflict-free LDS
    int tid = threadIdx.x;
    for (int i = tid; i < NEXP * DIN; i += blockDim.x) {
        int e = i / DIN, k = i % DIN;
        sgwT[i] = gw[k * NEXP + e];
    }
    __syncthreads();

    int warp = tid >> 5, lane = tid & 31;
    int base_tok = (blockIdx.x * 8 + warp) * 8;

    for (int t = 0; t < 8; t++) {
        int tok = base_tok + t;
        float acc[NEXP];
#pragma unroll
        for (int e = 0; e < NEXP; e++) acc[e] = 0.f;

        const float* xr = x + (size_t)tok * DIN;
        for (int k = lane; k < DIN; k += 32) {
            float xv = xr[k];
#pragma unroll
            for (int e = 0; e < NEXP; e++)
                acc[e] = fmaf(xv, sgwT[e * DIN + k], acc[e]);
        }
#pragma unroll
        for (int off = 16; off >= 1; off >>= 1) {
#pragma unroll
            for (int e = 0; e < NEXP; e++)
                acc[e] += __shfl_xor_sync(0xffffffffu, acc[e], off);
        }
        if (lane == 0) {
            // top-2 with lowest-index tie-break (matches jax.lax.top_k)
            float b1 = -1e30f, b2 = -1e30f; int i1 = 0, i2 = 0;
#pragma unroll
            for (int e = 0; e < NEXP; e++) {
                float v = acc[e] + gb[e];
                if (v > b1)      { b2 = b1; i2 = i1; b1 = v; i1 = e; }
                else if (v > b2) { b2 = v;  i2 = e; }
            }
            float ex  = expf(b2 - b1);          // <= 1
            float inv = 1.f / (1.f + ex);
            float w1 = inv, w2 = ex * inv;

            int p = atomicAdd(&g_cnt[i1], 1);
            g_perm[i1 * N_TOK + p] = tok;  g_pw[i1 * N_TOK + p] = w1;
            p = atomicAdd(&g_cnt[i2], 1);
            g_perm[i2 * N_TOK + p] = tok;  g_pw[i2 * N_TOK + p] = w2;
        }
    }
}

// ---------------- grouped expert GEMM: fp16 HMMA, fp32 accum -------------
// grid = (DOUT/BN, N_TOK/BM, NEXP); block = 256 threads (8 warps).
// Each block: 128 gathered tokens x 128 output cols for one expert.
__global__ void __launch_bounds__(256)
moe_gemm_kernel(const float* __restrict__ x,
                const float* __restrict__ ew,   // [E, DIN, DOUT]
                const float* __restrict__ eb,   // [E, DOUT]
                float* __restrict__ out) {
    int e  = blockIdx.z;
    int me = g_cnt[e];
    int m0 = blockIdx.y * BM;
    if (m0 >= me) return;
    int n0 = blockIdx.x * BN;

    __shared__ __half sA[BM][BK + 8];
    __shared__ __half sB[BK][BN + 8];
    __shared__ int    s_tok[BM];
    __shared__ float  s_w[BM];
    __shared__ float  s_out[8][16][20];   // ldm=20: multiple of 4 floats, 32B-aligned warp slices

    int tid = threadIdx.x;
    for (int i = tid; i < BM; i += 256) {
        int m = m0 + i;
        if (m < me) { s_tok[i] = g_perm[e * N_TOK + m]; s_w[i] = g_pw[e * N_TOK + m]; }
        else        { s_tok[i] = 0;                     s_w[i] = 0.f; }
    }
    __syncthreads();

    int warp = tid >> 5, lane = tid & 31;
    int wm = (warp >> 2) * 64;   // 2 warp-rows
    int wn = (warp & 3) * 32;    // 4 warp-cols

    wmma::fragment<wmma::accumulator, 16, 16, 16, float> accf[4][2];
#pragma unroll
    for (int i = 0; i < 4; i++)
#pragma unroll
        for (int j = 0; j < 2; j++) wmma::fill_fragment(accf[i][j], 0.f);

    const float* wpt = ew + (size_t)e * DIN * DOUT + n0;

    for (int k0 = 0; k0 < DIN; k0 += BK) {
        // A tile: 128 gathered rows x 32 k (fp32 -> fp16)
#pragma unroll
        for (int it = 0; it < 4; it++) {
            int idx = tid + it * 256;     // 0..1023 float4 slots
            int row = idx >> 3;           // 8 float4 per row
            int c4  = idx & 7;
            const float4 v = *(const float4*)(x + (size_t)s_tok[row] * DIN + k0 + c4 * 4);
            __half2* dst = (__half2*)&sA[row][c4 * 4];
            dst[0] = __floats2half2_rn(v.x, v.y);
            dst[1] = __floats2half2_rn(v.z, v.w);
        }
        // B tile: 32 k-rows x 128 n (fp32 -> fp16)
#pragma unroll
        for (int it = 0; it < 4; it++) {
            int idx = tid + it * 256;
            int kk  = idx >> 5;           // 32 float4 per row
            int c4  = idx & 31;
            const float4 v = *(const float4*)(wpt + (size_t)(k0 + kk) * DOUT + c4 * 4);
            __half2* dst = (__half2*)&sB[kk][c4 * 4];
            dst[0] = __floats2half2_rn(v.x, v.y);
            dst[1] = __floats2half2_rn(v.z, v.w);
        }
        __syncthreads();

#pragma unroll
        for (int kk = 0; kk < BK; kk += 16) {
            wmma::fragment<wmma::matrix_a, 16, 16, 16, __half, wmma::row_major> af[4];
            wmma::fragment<wmma::matrix_b, 16, 16, 16, __half, wmma::row_major> bf[2];
#pragma unroll
            for (int i = 0; i < 4; i++)
                wmma::load_matrix_sync(af[i], &sA[wm + i * 16][kk], BK + 8);
#pragma unroll
            for (int j = 0; j < 2; j++)
                wmma::load_matrix_sync(bf[j], &sB[kk][wn + j * 16], BN + 8);
#pragma unroll
            for (int i = 0; i < 4; i++)
#pragma unroll
                for (int j = 0; j < 2; j++)
                    wmma::mma_sync(accf[i][j], af[i], bf[j], accf[i][j]);
        }
        __syncthreads();
    }

    // epilogue: out[token, n] += w * (acc + bias)
    const float* bias = eb + (size_t)e * DOUT + n0;
#pragma unroll
    for (int i = 0; i < 4; i++) {
#pragma unroll
        for (int j = 0; j < 2; j++) {
            wmma::store_matrix_sync(&s_out[warp][0][0], accf[i][j], 20, wmma::mem_row_major);
            __syncwarp();
#pragma unroll
            for (int t = lane; t < 256; t += 32) {
                int r = t >> 4, c = t & 15;
                int row = wm + i * 16 + r;
                int col = wn + j * 16 + c;
                float w = s_w[row];
                if (w != 0.f) {
                    float v = w * (s_out[warp][r][c] + bias[col]);
                    atomicAdd(&out[(size_t)s_tok[row] * DOUT + n0 + col], v);
                }
            }
            __syncwarp();
        }
    }
}

// ---------------- launch -------------------------------------------------
extern "C" void kernel_launch(void* const* d_in, const int* in_sizes, int n_in,
                              void* d_out, int out_size) {
    const float* x  = (const float*)d_in[0];   // [16384, 512]
    const float* gw = (const float*)d_in[1];   // [512, 16]
    const float* gb = (const float*)d_in[2];   // [16]
    const float* ew = (const float*)d_in[3];   // [16, 512, 512]
    const float* eb = (const float*)d_in[4];   // [16, 512]
    float* out = (float*)d_out;                // [16384, 512]

    cudaMemsetAsync(out, 0, (size_t)N_TOK * DOUT * sizeof(float));
    zero_cnt_kernel<<<1, 32>>>();
    router_kernel<<<N_TOK / 64, 256>>>(x, gw, gb);

    dim3 grid(DOUT / BN, N_TOK / BM, NEXP);    // (4, 128, 16); empty tiles exit early
    moe_gemm_kernel<<<grid, 256>>>(x, ew, eb, out);
}

// round 5
// speedup vs baseline: 1.3916x; 1.3916x over previous
#include <cuda_runtime.h>
#include <cuda_fp16.h>
#include <mma.h>
#include <cstdint>

using namespace nvcuda;

#define N_TOK 16384
#define DIN   512
#define DOUT  512
#define NEXP  16

#define BM 128
#define BN 128
#define BK 32
#define NIT (DIN / BK)   // 16

// ---------------- device scratch (no allocations allowed) ----------------
__device__ int    g_cnt[NEXP];
__device__ int    g_perm[NEXP * N_TOK];
__device__ float  g_pw  [NEXP * N_TOK];
__device__ __half g_xh [N_TOK * DIN];          // fp16 copy of x
__device__ __half g_ewh[NEXP * DIN * DOUT];    // fp16 copy of expert_w

// ---------------- fp32 -> fp16 preconversion (+ zero counters) ----------
__global__ void convert_kernel(const float* __restrict__ x,
                               const float* __restrict__ ew) {
    if (blockIdx.x == 0 && threadIdx.x < NEXP) g_cnt[threadIdx.x] = 0;

    const int nx = N_TOK * DIN / 4;            // float4 count for x
    const int nw = NEXP * DIN * DOUT / 4;      // float4 count for ew
    int stride = gridDim.x * blockDim.x;
    for (int i = blockIdx.x * blockDim.x + threadIdx.x; i < nx + nw; i += stride) {
        if (i < nx) {
            float4 v = ((const float4*)x)[i];
            __half2* dst = (__half2*)(g_xh + (size_t)i * 4);
            dst[0] = __floats2half2_rn(v.x, v.y);
            dst[1] = __floats2half2_rn(v.z, v.w);
        } else {
            int j = i - nx;
            float4 v = ((const float4*)ew)[j];
            __half2* dst = (__half2*)(g_ewh + (size_t)j * 4);
            dst[0] = __floats2half2_rn(v.x, v.y);
            dst[1] = __floats2half2_rn(v.z, v.w);
        }
    }
}

// ---------------- router: fp32 logits, top-2 + softmax, scatter ----------
__global__ void router_kernel(const float* __restrict__ x,
                              const float* __restrict__ gw,   // [DIN, NEXP]
                              const float* __restrict__ gb) { // [NEXP]
    __shared__ float sgwT[NEXP * DIN];
    int tid = threadIdx.x;
    for (int i = tid; i < NEXP * DIN; i += blockDim.x) {
        int e = i / DIN, k = i % DIN;
        sgwT[i] = gw[k * NEXP + e];
    }
    __syncthreads();

    int warp = tid >> 5, lane = tid & 31;
    int base_tok = (blockIdx.x * 8 + warp) * 8;

    for (int t = 0; t < 8; t++) {
        int tok = base_tok + t;
        float acc[NEXP];
#pragma unroll
        for (int e = 0; e < NEXP; e++) acc[e] = 0.f;

        const float* xr = x + (size_t)tok * DIN;
        for (int k = lane; k < DIN; k += 32) {
            float xv = xr[k];
#pragma unroll
            for (int e = 0; e < NEXP; e++)
                acc[e] = fmaf(xv, sgwT[e * DIN + k], acc[e]);
        }
#pragma unroll
        for (int off = 16; off >= 1; off >>= 1) {
#pragma unroll
            for (int e = 0; e < NEXP; e++)
                acc[e] += __shfl_xor_sync(0xffffffffu, acc[e], off);
        }
        if (lane == 0) {
            float b1 = -1e30f, b2 = -1e30f; int i1 = 0, i2 = 0;
#pragma unroll
            for (int e = 0; e < NEXP; e++) {
                float v = acc[e] + gb[e];
                if (v > b1)      { b2 = b1; i2 = i1; b1 = v; i1 = e; }
                else if (v > b2) { b2 = v;  i2 = e; }
            }
            float ex  = expf(b2 - b1);
            float inv = 1.f / (1.f + ex);
            float w1 = inv, w2 = ex * inv;

            int p = atomicAdd(&g_cnt[i1], 1);
            g_perm[i1 * N_TOK + p] = tok;  g_pw[i1 * N_TOK + p] = w1;
            p = atomicAdd(&g_cnt[i2], 1);
            g_perm[i2 * N_TOK + p] = tok;  g_pw[i2 * N_TOK + p] = w2;
        }
    }
}

// ---------------- cp.async helper ---------------------------------------
__device__ __forceinline__ void cp_async16(void* smem_dst, const void* gmem_src) {
    unsigned int s = (unsigned int)__cvta_generic_to_shared(smem_dst);
    asm volatile("cp.async.cg.shared.global [%0], [%1], 16;\n"
                 :: "r"(s), "l"(gmem_src));
}
__device__ __forceinline__ void cp_async_commit() {
    asm volatile("cp.async.commit_group;\n");
}
__device__ __forceinline__ void cp_async_wait1() {
    asm volatile("cp.async.wait_group 1;\n");
}

// ---------------- grouped expert GEMM: fp16 HMMA, fp32 accum, 2-stage ----
// grid = (DOUT/BN, N_TOK/BM, NEXP); block = 256 threads (8 warps).
__global__ void __launch_bounds__(256)
moe_gemm_kernel(const float* __restrict__ eb,   // [E, DOUT]
                float* __restrict__ out) {
    int e  = blockIdx.z;
    int me = g_cnt[e];
    int m0 = blockIdx.y * BM;
    if (m0 >= me) return;
    int n0 = blockIdx.x * BN;

    // sA buffer is reused as the epilogue staging area (union).
    __shared__ union {
        __half a[2][BM][BK + 8];      // 20480 B
        float  o[8][16][20];          // 10240 B
    } uA;
    __shared__ __half sB[2][BK][BN + 8];   // 17408 B
    __shared__ int    s_tok[BM];
    __shared__ float  s_w[BM];

    int tid = threadIdx.x;
    for (int i = tid; i < BM; i += 256) {
        int m = m0 + i;
        if (m < me) { s_tok[i] = g_perm[e * N_TOK + m]; s_w[i] = g_pw[e * N_TOK + m]; }
        else        { s_tok[i] = 0;                     s_w[i] = 0.f; }
    }
    __syncthreads();

    const __half* wpt = g_ewh + (size_t)e * DIN * DOUT + n0;

    // ---- pipeline prefetch: stage `st` loads k0 = it*BK ----
    auto prefetch = [&](int it, int st) {
        int k0 = it * BK;
        // A: 128 rows x 32 halves = 4 x 16B chunks per row -> 512 chunks
#pragma unroll
        for (int i = 0; i < 2; i++) {
            int idx = tid + i * 256;
            int row = idx >> 2, c = idx & 3;
            cp_async16(&uA.a[st][row][c * 8],
                       g_xh + (size_t)s_tok[row] * DIN + k0 + c * 8);
        }
        // B: 32 rows x 128 halves = 16 x 16B chunks per row -> 512 chunks
#pragma unroll
        for (int i = 0; i < 2; i++) {
            int idx = tid + i * 256;
            int kk = idx >> 4, c = idx & 15;
            cp_async16(&sB[st][kk][c * 8],
                       wpt + (size_t)(k0 + kk) * DOUT + c * 8);
        }
    };

    int warp = tid >> 5, lane = tid & 31;
    int wm = (warp >> 2) * 64;   // 2 warp-rows of 64
    int wn = (warp & 3) * 32;    // 4 warp-cols of 32

    wmma::fragment<wmma::accumulator, 16, 16, 16, float> accf[4][2];
#pragma unroll
    for (int i = 0; i < 4; i++)
#pragma unroll
        for (int j = 0; j < 2; j++) wmma::fill_fragment(accf[i][j], 0.f);

    prefetch(0, 0);
    cp_async_commit();

    for (int it = 0; it < NIT; it++) {
        int st = it & 1;
        if (it + 1 < NIT) prefetch(it + 1, st ^ 1);
        cp_async_commit();
        cp_async_wait1();      // stage `st` data resident
        __syncthreads();

#pragma unroll
        for (int kk = 0; kk < BK; kk += 16) {
            wmma::fragment<wmma::matrix_a, 16, 16, 16, __half, wmma::row_major> af[4];
            wmma::fragment<wmma::matrix_b, 16, 16, 16, __half, wmma::row_major> bf[2];
#pragma unroll
            for (int i = 0; i < 4; i++)
                wmma::load_matrix_sync(af[i], &uA.a[st][wm + i * 16][kk], BK + 8);
#pragma unroll
            for (int j = 0; j < 2; j++)
                wmma::load_matrix_sync(bf[j], &sB[st][kk][wn + j * 16], BN + 8);
#pragma unroll
            for (int i = 0; i < 4; i++)
#pragma unroll
                for (int j = 0; j < 2; j++)
                    wmma::mma_sync(accf[i][j], af[i], bf[j], accf[i][j]);
        }
        __syncthreads();       // stage `st` consumed; safe to overwrite next iter
    }

    // ---- epilogue: out[token, n] += w * (acc + bias) ----
    __syncthreads();           // done with uA.a before aliasing as uA.o
    const float* bias = eb + (size_t)e * DOUT + n0;
#pragma unroll
    for (int i = 0; i < 4; i++) {
#pragma unroll
        for (int j = 0; j < 2; j++) {
            wmma::store_matrix_sync(&uA.o[warp][0][0], accf[i][j], 20, wmma::mem_row_major);
            __syncwarp();
#pragma unroll
            for (int t = lane; t < 256; t += 32) {
                int r = t >> 4, c = t & 15;
                int row = wm + i * 16 + r;
                int col = wn + j * 16 + c;
                float w = s_w[row];
                if (w != 0.f) {
                    float v = w * (uA.o[warp][r][c] + bias[col]);
                    atomicAdd(&out[(size_t)s_tok[row] * DOUT + n0 + col], v);
                }
            }
            __syncwarp();
        }
    }
}

// ---------------- launch -------------------------------------------------
extern "C" void kernel_launch(void* const* d_in, const int* in_sizes, int n_in,
                              void* d_out, int out_size) {
    const float* x  = (const float*)d_in[0];   // [16384, 512]
    const float* gw = (const float*)d_in[1];   // [512, 16]
    const float* gb = (const float*)d_in[2];   // [16]
    const float* ew = (const float*)d_in[3];   // [16, 512, 512]
    const float* eb = (const float*)d_in[4];   // [16, 512]
    float* out = (float*)d_out;                // [16384, 512]

    cudaMemsetAsync(out, 0, (size_t)N_TOK * DOUT * sizeof(float));
    convert_kernel<<<1024, 256>>>(x, ew);      // also zeroes g_cnt
    router_kernel<<<N_TOK / 64, 256>>>(x, gw, gb);

    dim3 grid(DOUT / BN, N_TOK / BM, NEXP);    // (4, 128, 16)
    moe_gemm_kernel<<<grid, 256>>>(eb, out);
}